// round 1
// baseline (speedup 1.0000x reference)
#include <cuda_runtime.h>

#define FULLM 0xFFFFFFFFu

namespace {

constexpr int S_      = 50;
constexpr int WARPS_  = 8;
constexpr int RPW_    = 4;                 // rows per warp
constexpr int THREADS_= WARPS_ * 32;

// ---- per-warp shared layout (float offsets, 16B-aligned where needed) ----
constexpr int XO_  = 0;      // x[50][16] quad-swizzled        (800)
constexpr int WTO_ = 800;    // wT[4][52] softmax weights      (208)
constexpr int IDO_ = 1008;   // ids[52] (ints)                 (52)
constexpr int UO_  = 1060;   // uE[16]
constexpr int IEO_ = 1076;   // iE[16]
constexpr int TGO_ = 1092;   // targetS[16]
constexpr int QO_  = 1108;   // q[16]
constexpr int RKO_ = 1124;   // rk[4][16]
constexpr int RBO_ = 1188;   // rb[4]
constexpr int LIO_ = 1192;   // 1/l [4]
constexpr int CO_  = 1196;   // c[4][16]
constexpr int ATO_ = 1260;   // att[16]
constexpr int HDO_ = 1276;   // hidden[16] (reused)
constexpr int THO_ = 1292;   // teacher[16]
constexpr int WSZ_ = 1344;   // per-warp size (floats)

// ---- weight region (shared, block-wide) ----
constexpr int O_ESW1=0,    O_ESB1=256,  O_ESW2=272,  O_ESB2=528;
constexpr int O_ETW1=544,  O_ETB1=1056, O_ETW2=1072, O_ETB2=1328;
constexpr int O_DCW1=1344, O_DCB1=1856, O_DCW2=1872, O_DCB2=2128;
constexpr int O_QW=2144,   O_QB=2400,   O_KW=2416,   O_KB=2672;
constexpr int O_VW=2688,   O_VB=2944,   O_STW=2960,  O_STB=2976;
constexpr int O_AUX=2977;  // 8 aux slots
constexpr int WGT_ = 2992; // weight region size (floats)

constexpr int SMEM_FLOATS = WGT_ + WARPS_ * WSZ_;

struct P {
  const int *users, *items, *sids;
  const float *user_emb, *item_emb, *user_lin, *item_lin, *slate_emb;
  const float *es_w1, *es_b1, *es_w2, *es_b2;
  const float *et_w1, *et_b1, *et_w2, *et_b2;
  const float *dec_w1, *dec_b1, *dec_w2, *dec_b2;
  const float *q_w, *q_b, *k_w, *k_b, *v_w, *v_b, *st_w, *st_b;
  float* out;
  int B;
  int out_size;
};

} // namespace

extern __shared__ float sm[];

__device__ __forceinline__ float dot4(float4 a, float4 b) {
  return a.x*b.x + a.y*b.y + a.z*b.z + a.w*b.w;
}

__global__ __launch_bounds__(THREADS_, 3)
void fmslate_kernel(P p) {
  const int tid  = threadIdx.x;
  const int warp = tid >> 5;
  const int lane = tid & 31;
  const int j16  = lane & 15;
  const int half = lane >> 4;

  // ---- stage weights into shared (once per block) ----
#define CPW(off, src, n) for (int i = tid; i < (n); i += THREADS_) sm[(off)+i] = (src)[i];
  CPW(O_ESW1, p.es_w1, 256)  CPW(O_ESB1, p.es_b1, 16)
  CPW(O_ESW2, p.es_w2, 256)  CPW(O_ESB2, p.es_b2, 16)
  CPW(O_ETW1, p.et_w1, 512)  CPW(O_ETB1, p.et_b1, 16)
  CPW(O_ETW2, p.et_w2, 256)  CPW(O_ETB2, p.et_b2, 16)
  CPW(O_DCW1, p.dec_w1, 512) CPW(O_DCB1, p.dec_b1, 16)
  CPW(O_DCW2, p.dec_w2, 256) CPW(O_DCB2, p.dec_b2, 16)
  CPW(O_QW,   p.q_w,   256)  CPW(O_QB,   p.q_b,   16)
  CPW(O_KW,   p.k_w,   256)  CPW(O_KB,   p.k_b,   16)
  CPW(O_VW,   p.v_w,   256)  CPW(O_VB,   p.v_b,   16)
  CPW(O_STW,  p.st_w,  16)   CPW(O_STB,  p.st_b,  1)
#undef CPW
  __syncthreads();

  float* ws    = sm + WGT_ + warp * WSZ_;
  float* xw    = ws + XO_;
  float* wT    = ws + WTO_;
  int*   ids   = (int*)(ws + IDO_);
  float* u_sh  = ws + UO_;
  float* ie_sh = ws + IEO_;
  float* tg_sh = ws + TGO_;
  float* q_sh  = ws + QO_;
  float* rk_sh = ws + RKO_;
  float* rb_sh = ws + RBO_;
  float* li_sh = ws + LIO_;
  float* c_sh  = ws + CO_;
  float* at_sh = ws + ATO_;
  float* hd_sh = ws + HDO_;
  float* th_sh = ws + THO_;

  const int gw = blockIdx.x * WARPS_ + warp;
  float auxAcc = 0.f;

  for (int r = 0; r < RPW_; r++) {
    const int row = gw * RPW_ + r;
    if (row >= p.B) break;

    const int user = p.users[row];
    const int item = p.items[row];

    // ---- gather small vectors (float4 per lane, lanes 0..11) ----
    if (lane < 4)
      ((float4*)u_sh)[lane]      = ((const float4*)(p.user_emb  + (size_t)user*16))[lane];
    else if (lane < 8)
      ((float4*)ie_sh)[lane-4]   = ((const float4*)(p.item_emb  + (size_t)item*16))[lane-4];
    else if (lane < 12)
      ((float4*)tg_sh)[lane-8]   = ((const float4*)(p.slate_emb + (size_t)item*16))[lane-8];

    // ---- stage slate ids ----
    const int* sp = p.sids + (size_t)row * S_;
    if (lane < S_)      ids[lane]      = sp[lane];
    if (lane + 32 < S_) ids[lane + 32] = sp[lane + 32];
    __syncwarp();

    // ---- gather slate embeddings, quad-rotation swizzle into shared ----
    for (int t = lane; t < S_ * 4; t += 32) {
      const int s  = t >> 2;
      const int qd = t & 3;
      const int rr = ids[s];
      float4 v = ((const float4*)(p.slate_emb + (size_t)rr * 16))[qd];
      const int ph = (qd + (s >> 1)) & 3;
      *((float4*)(xw + s * 16 + ph * 4)) = v;
    }
    __syncwarp();

    // ---- q projection (both halves compute, half 0 writes) ----
    float qv = sm[O_QB + j16];
    #pragma unroll
    for (int d = 0; d < 16; d++) qv = fmaf(tg_sh[d], sm[O_QW + d*16 + j16], qv);
    if (half == 0) q_sh[j16] = qv;
    __syncwarp();

    // ---- rk[h][d] = 0.5 * sum_e k_w[d][4h+e] * q[4h+e];  rb[h] from k_b ----
    #pragma unroll
    for (int rr = 0; rr < 2; rr++) {
      const int idx = lane + rr * 32;
      const int h = idx >> 4, d = idx & 15;
      float acc = 0.f;
      #pragma unroll
      for (int e = 0; e < 4; e++)
        acc = fmaf(sm[O_KW + d*16 + h*4 + e], q_sh[h*4 + e], acc);
      rk_sh[h*16 + d] = 0.5f * acc;
    }
    if (lane < 4) {
      float acc = 0.f;
      #pragma unroll
      for (int e = 0; e < 4; e++)
        acc = fmaf(q_sh[lane*4 + e], sm[O_KB + lane*4 + e], acc);
      rb_sh[lane] = 0.5f * acc;
    }
    __syncwarp();

    // ---- logits: lane -> (h = lane&3, s = lane>>2 + 8k) ----
    const int h  = lane & 3;
    const int sb = lane >> 2;
    const float4* rkq = (const float4*)(rk_sh + h * 16);
    const float4 rk0 = rkq[0], rk1 = rkq[1], rk2 = rkq[2], rk3 = rkq[3];
    const float rbh = rb_sh[h];

    float lg[7];
    float m = -1e30f;
    {
      int cnt = 0;
      for (int s = sb; s < S_; s += 8, cnt++) {
        const float4* xb = (const float4*)(xw + s * 16);
        const int rot = (s >> 1) & 3;
        float4 x0 = xb[rot];
        float4 x1 = xb[(rot + 1) & 3];
        float4 x2 = xb[(rot + 2) & 3];
        float4 x3 = xb[(rot + 3) & 3];
        float l = rbh + dot4(x0, rk0) + dot4(x1, rk1) + dot4(x2, rk2) + dot4(x3, rk3);
        lg[cnt] = l;
        m = fmaxf(m, l);
      }
    }
    #pragma unroll
    for (int o = 4; o < 32; o <<= 1) m = fmaxf(m, __shfl_xor_sync(FULLM, m, o));

    float ssum = 0.f;
    {
      int cnt = 0;
      for (int s = sb; s < S_; s += 8, cnt++) {
        float e = __expf(lg[cnt] - m);
        wT[h * 52 + s] = e;
        ssum += e;
      }
    }
    #pragma unroll
    for (int o = 4; o < 32; o <<= 1) ssum += __shfl_xor_sync(FULLM, ssum, o);
    if (lane < 4) li_sh[lane] = 1.0f / ssum;
    __syncwarp();

    // ---- c[h][d] = sum_s w[h][s] * x[s][d]  (each half does 2 heads) ----
    {
      const int d    = j16;
      const int h0   = half * 2;
      const int h1   = h0 + 1;
      const int quad = d >> 2;
      const int doff = d & 3;
      float c0 = 0.f, c1 = 0.f;
      for (int s4 = 0; s4 < 12; s4++) {
        float wa0[4], wa1[4];
        *(float4*)wa0 = *(const float4*)&wT[h0*52 + s4*4];
        *(float4*)wa1 = *(const float4*)&wT[h1*52 + s4*4];
        #pragma unroll
        for (int k = 0; k < 4; k++) {
          const int ss = s4*4 + k;
          const int ph = (quad + (ss >> 1)) & 3;
          float xv = xw[ss*16 + ph*4 + doff];
          c0 = fmaf(wa0[k], xv, c0);
          c1 = fmaf(wa1[k], xv, c1);
        }
      }
      #pragma unroll
      for (int ss = 48; ss < 50; ss++) {
        const int ph = (quad + (ss >> 1)) & 3;
        float xv = xw[ss*16 + ph*4 + doff];
        c0 = fmaf(wT[h0*52 + ss], xv, c0);
        c1 = fmaf(wT[h1*52 + ss], xv, c1);
      }
      c0 *= li_sh[h0];
      c1 *= li_sh[h1];
      c_sh[h0*16 + d] = c0;
      c_sh[h1*16 + d] = c1;
    }
    __syncwarp();

    // ---- att[j] = v_b[j] + sum_d c[h(j)][d] * v_w[d][j] ----
    {
      const int hj = j16 >> 2;
      float att = sm[O_VB + j16];
      #pragma unroll
      for (int d = 0; d < 16; d++)
        att = fmaf(c_sh[hj*16 + d], sm[O_VW + d*16 + j16], att);
      if (half == 0) at_sh[j16] = att;
    }
    __syncwarp();

    // ---- student MLP ----
    float s1 = sm[O_ESB1 + j16];
    #pragma unroll
    for (int d = 0; d < 16; d++) s1 = fmaf(u_sh[d], sm[O_ESW1 + d*16 + j16], s1);
    s1 = fmaxf(s1, 0.f);
    if (half == 0) hd_sh[j16] = s1;
    __syncwarp();
    float stud = sm[O_ESB2 + j16];
    #pragma unroll
    for (int d = 0; d < 16; d++) stud = fmaf(hd_sh[d], sm[O_ESW2 + d*16 + j16], stud);
    __syncwarp();

    // ---- teacher MLP: input = [uE, att] ----
    float t1 = sm[O_ETB1 + j16];
    #pragma unroll
    for (int d = 0; d < 16; d++) t1 = fmaf(u_sh[d],  sm[O_ETW1 + d*16 + j16], t1);
    #pragma unroll
    for (int d = 0; d < 16; d++) t1 = fmaf(at_sh[d], sm[O_ETW1 + (16+d)*16 + j16], t1);
    t1 = fmaxf(t1, 0.f);
    if (half == 0) hd_sh[j16] = t1;
    __syncwarp();
    float teach = sm[O_ETB2 + j16];
    #pragma unroll
    for (int d = 0; d < 16; d++) teach = fmaf(hd_sh[d], sm[O_ETW2 + d*16 + j16], teach);
    if (half == 0) th_sh[j16] = teach;

    // reg contribution: sum_j (stud - teach)^2  (width-16 reduce)
    float diff = stud - teach;
    float regp = diff * diff;
    #pragma unroll
    for (int o = 1; o < 16; o <<= 1) regp += __shfl_xor_sync(FULLM, regp, o);
    __syncwarp();

    // ---- decoder MLP: input = [uE, teacher] ----
    float d1 = sm[O_DCB1 + j16];
    #pragma unroll
    for (int d = 0; d < 16; d++) d1 = fmaf(u_sh[d],  sm[O_DCW1 + d*16 + j16], d1);
    #pragma unroll
    for (int d = 0; d < 16; d++) d1 = fmaf(th_sh[d], sm[O_DCW1 + (16+d)*16 + j16], d1);
    d1 = fmaxf(d1, 0.f);
    __syncwarp();
    if (half == 0) hd_sh[j16] = d1;
    __syncwarp();
    float isl = sm[O_DCB2 + j16];
    #pragma unroll
    for (int d = 0; d < 16; d++) isl = fmaf(hd_sh[d], sm[O_DCW2 + d*16 + j16], isl);

    // slate_term = input_slate @ st_w + st_b
    float sp2 = isl * sm[O_STW + j16];
    #pragma unroll
    for (int o = 1; o < 16; o <<= 1) sp2 += __shfl_xor_sync(FULLM, sp2, o);
    const float slate_term = sp2 + sm[O_STB];

    // fm_term = dot(uE, iE)
    float fmp = u_sh[j16] * ie_sh[j16];
    #pragma unroll
    for (int o = 1; o < 16; o <<= 1) fmp += __shfl_xor_sync(FULLM, fmp, o);

    const float uL = p.user_lin[user];
    const float iL = p.item_lin[item];
    const float lo = uL + iL + fmp + slate_term;
    const float outv = 1.0f / (1.0f + __expf(-lo));
    if (lane == 0) p.out[row] = outv;

    const float tq = fmp + slate_term;
    auxAcc += regp + 0.1f * tq * tq;
    __syncwarp();
  }

  // ---- aux reduction (reg_loss mean + 0.1 * mean(sq)) ----
  if (p.out_size > p.B) {
    if (lane == 0) sm[O_AUX + warp] = auxAcc;
    __syncthreads();
    if (warp == 0) {
      float v = (lane < WARPS_) ? sm[O_AUX + lane] : 0.f;
      #pragma unroll
      for (int o = 1; o < WARPS_; o <<= 1) v += __shfl_xor_sync(FULLM, v, o);
      if (lane == 0) atomicAdd(p.out + p.B, v * (1.0f / (float)p.B));
    }
  }
}

extern "C" void kernel_launch(void* const* d_in, const int* in_sizes, int n_in,
                              void* d_out, int out_size) {
  P p;
  p.users     = (const int*)  d_in[0];
  p.items     = (const int*)  d_in[1];
  p.sids      = (const int*)  d_in[2];
  // d_in[3] slate_poses, d_in[4] slate_ratings: unused by reference
  p.user_emb  = (const float*)d_in[5];
  p.item_emb  = (const float*)d_in[6];
  p.user_lin  = (const float*)d_in[7];
  p.item_lin  = (const float*)d_in[8];
  p.slate_emb = (const float*)d_in[9];
  p.es_w1  = (const float*)d_in[10]; p.es_b1  = (const float*)d_in[11];
  p.es_w2  = (const float*)d_in[12]; p.es_b2  = (const float*)d_in[13];
  p.et_w1  = (const float*)d_in[14]; p.et_b1  = (const float*)d_in[15];
  p.et_w2  = (const float*)d_in[16]; p.et_b2  = (const float*)d_in[17];
  p.dec_w1 = (const float*)d_in[18]; p.dec_b1 = (const float*)d_in[19];
  p.dec_w2 = (const float*)d_in[20]; p.dec_b2 = (const float*)d_in[21];
  p.q_w    = (const float*)d_in[22]; p.q_b    = (const float*)d_in[23];
  p.k_w    = (const float*)d_in[24]; p.k_b    = (const float*)d_in[25];
  p.v_w    = (const float*)d_in[26]; p.v_b    = (const float*)d_in[27];
  p.st_w   = (const float*)d_in[28]; p.st_b   = (const float*)d_in[29];
  p.out      = (float*)d_out;
  p.B        = in_sizes[0];
  p.out_size = out_size;

  const int smemBytes = SMEM_FLOATS * (int)sizeof(float);
  cudaFuncSetAttribute(fmslate_kernel,
                       cudaFuncAttributeMaxDynamicSharedMemorySize, smemBytes);

  if (out_size > p.B) {
    cudaMemsetAsync((float*)d_out + p.B, 0, sizeof(float));
  }

  const int rowsPerBlock = WARPS_ * RPW_;
  const int grid = (p.B + rowsPerBlock - 1) / rowsPerBlock;
  fmslate_kernel<<<grid, THREADS_, smemBytes>>>(p);
}